// round 6
// baseline (speedup 1.0000x reference)
#include <cuda_runtime.h>
#include <cuda_bf16.h>
#include <cstdint>

// ---------------------------------------------------------------------------
// RecurrentRetention: B=16, T=2048, D=256, gamma=0.9
//   vsum[b,t] = x[b,t,:].rowsum(Wv);  y[t,e] = sum_b vsum[b,t]*x[b,t,e]
//   c = y @ Wk;  r[t] = 0.9 r[t-1] + c[t] (exact 3-phase scan) -> S
//   out[b,q,p] = S[8p+(q>>8), q&255] * (x @ Wq)[b,q,p]
// Both GEMMs via warp-level mma.sync bf16, split fp32 = hi + lo
// (D = Ah*Bh + Ah*Bl + Al*Bh). A split happens in-kernel from fp32.
// ---------------------------------------------------------------------------

#define Bsz 16
#define T   2048
#define D   256
#define LTILE 16
#define NTILE (T / LTILE)             // 128
#define G16 0.1853020188851841f       // 0.9^16

__device__ float g_wvsum[D];
__device__ float g_y[T * D];
__device__ float g_c[T * D];
__device__ float g_S[T * D];
__device__ float g_carry[NTILE * D];
__device__ float g_pref[NTILE * D];
__device__ __nv_bfloat16 g_bqh[D * D];  // Wq^T hi, [n][k]
__device__ __nv_bfloat16 g_bql[D * D];  // Wq^T lo
__device__ __nv_bfloat16 g_bkh[D * D];  // Wk^T hi
__device__ __nv_bfloat16 g_bkl[D * D];  // Wk^T lo

__device__ __forceinline__ uint32_t smem_u32(const void* p) {
    uint32_t a;
    asm("{ .reg .u64 t; cvta.to.shared.u64 t, %1; cvt.u32.u64 %0, t; }" : "=r"(a) : "l"(p));
    return a;
}
__device__ __forceinline__ void ldm_x4(uint32_t* r, uint32_t addr) {
    asm volatile("ldmatrix.sync.aligned.m8n8.x4.shared.b16 {%0,%1,%2,%3}, [%4];"
        : "=r"(r[0]), "=r"(r[1]), "=r"(r[2]), "=r"(r[3]) : "r"(addr));
}
__device__ __forceinline__ void ldm_x2(uint32_t* r, uint32_t addr) {
    asm volatile("ldmatrix.sync.aligned.m8n8.x2.shared.b16 {%0,%1}, [%2];"
        : "=r"(r[0]), "=r"(r[1]) : "r"(addr));
}
__device__ __forceinline__ void mma_bf16(float* c, const uint32_t* a, const uint32_t* b) {
    asm volatile(
        "mma.sync.aligned.m16n8k16.row.col.f32.bf16.bf16.f32 "
        "{%0,%1,%2,%3}, {%4,%5,%6,%7}, {%8,%9}, {%0,%1,%2,%3};"
        : "+f"(c[0]), "+f"(c[1]), "+f"(c[2]), "+f"(c[3])
        : "r"(a[0]), "r"(a[1]), "r"(a[2]), "r"(a[3]), "r"(b[0]), "r"(b[1]));
}
// split two floats into packed bf16x2 hi / lo
__device__ __forceinline__ void split2(float a, float b, uint32_t& h, uint32_t& l) {
    __nv_bfloat16 ha = __float2bfloat16(a), hb = __float2bfloat16(b);
    __nv_bfloat16 la = __float2bfloat16(a - __bfloat162float(ha));
    __nv_bfloat16 lb = __float2bfloat16(b - __bfloat162float(hb));
    __nv_bfloat162 th(ha, hb), tl(la, lb);
    h = *(uint32_t*)&th;
    l = *(uint32_t*)&tl;
}

// ======================= prep: wvsum + Wq/Wk transpose-split ===============
__global__ void prep_kernel(const float* __restrict__ Wq, const float* __restrict__ Wk,
                            const float* __restrict__ Wv) {
    int bx = blockIdx.x, tid = threadIdx.x;
    if (bx < 256) {                       // Wq^T split
        int k = bx, n = tid;
        float w = Wq[k * D + n];
        __nv_bfloat16 h = __float2bfloat16(w);
        g_bqh[n * D + k] = h;
        g_bql[n * D + k] = __float2bfloat16(w - __bfloat162float(h));
    } else if (bx < 512) {                // Wk^T split
        int k = bx - 256, n = tid;
        float w = Wk[k * D + n];
        __nv_bfloat16 h = __float2bfloat16(w);
        g_bkh[n * D + k] = h;
        g_bkl[n * D + k] = __float2bfloat16(w - __bfloat162float(h));
    } else {                              // wvsum rows
        int row  = (bx - 512) * 8 + (tid >> 5);
        int lane = tid & 31;
        float p = 0.f;
        #pragma unroll
        for (int j = lane; j < D; j += 32) p += Wv[row * D + j];
        #pragma unroll
        for (int off = 16; off; off >>= 1) p += __shfl_xor_sync(0xffffffffu, p, off);
        if (lane == 0) g_wvsum[row] = p;
    }
}

// ======================= y kernel ==========================================
__global__ void y_kernel(const float* __restrict__ x) {
    __shared__ float xs[Bsz][D];
    __shared__ float vs[Bsz];
    __shared__ float wv[D];
    int t = blockIdx.x;
    int e = threadIdx.x;

    wv[e] = g_wvsum[e];
    #pragma unroll
    for (int b = 0; b < Bsz; ++b)
        xs[b][e] = x[((size_t)b * T + t) * D + e];
    __syncthreads();

    int warp = e >> 5, lane = e & 31;
    #pragma unroll
    for (int rep = 0; rep < 2; ++rep) {
        int b = warp * 2 + rep;
        float p = 0.f;
        #pragma unroll
        for (int k = lane; k < D; k += 32) p += xs[b][k] * wv[k];
        #pragma unroll
        for (int off = 16; off; off >>= 1) p += __shfl_xor_sync(0xffffffffu, p, off);
        if (lane == 0) vs[b] = p;
    }
    __syncthreads();

    float acc = 0.f;
    #pragma unroll
    for (int b = 0; b < Bsz; ++b) acc += vs[b] * xs[b][e];
    g_y[t * D + e] = acc;
}

// ======================= unified mma GEMM ==================================
// C[m,n] = sum_k A[m,k]*Bt[n,k]; A fp32 (split in-kernel), Bt pre-split bf16.
// CTA tile (MF*32) x 128, 8 warps = 2(m) x 4(n), warp tile (MF*16) x 32.
// If SCALE: multiply by S[8n + (q>>8), q&255], q = m & 2047.
#define ROWB 80
template<int MF, bool SCALE>
__global__ void __launch_bounds__(256, 2)
gemm_mma(const float* __restrict__ A,
         const __nv_bfloat16* __restrict__ bth, const __nv_bfloat16* __restrict__ btl,
         float* __restrict__ C) {
    __shared__ char sAh[MF * 32 * ROWB], sAl[MF * 32 * ROWB];
    __shared__ char sBh[128 * ROWB],     sBl[128 * ROWB];

    int tid = threadIdx.x, wid = tid >> 5, lane = tid & 31;
    int m0 = blockIdx.x * (MF * 32), n0 = blockIdx.y * 128;
    int mwarp = (wid & 1) * (MF * 16), nwarp = (wid >> 1) * 32;

    uint32_t uAh = smem_u32(sAh), uAl = smem_u32(sAl);
    uint32_t uBh = smem_u32(sBh), uBl = smem_u32(sBl);

    float acc[MF][4][4] = {};

    int arow = lane & 15, ao16 = (lane >> 4) * 16;
    int brow = lane & 7,  bo16 = ((lane >> 3) & 1) * 16;

    for (int kc = 0; kc < 8; ++kc) {
        __syncthreads();
        // A chunk [MF*32 x 32] fp32 -> split to smem hi/lo
        #pragma unroll
        for (int j = 0; j < MF; ++j) {
            int i = tid + j * 256;            // float4 index
            int r = i >> 3, c4 = i & 7;
            float4 v = *(const float4*)(A + (size_t)(m0 + r) * 256 + kc * 32 + c4 * 4);
            uint32_t h01, l01, h23, l23;
            split2(v.x, v.y, h01, l01);
            split2(v.z, v.w, h23, l23);
            uint32_t so = r * ROWB + c4 * 8;
            *(uint32_t*)(sAh + so)     = h01;
            *(uint32_t*)(sAh + so + 4) = h23;
            *(uint32_t*)(sAl + so)     = l01;
            *(uint32_t*)(sAl + so + 4) = l23;
        }
        // B chunk [128 x 32] bf16 hi/lo (pre-split, [n][k])
        #pragma unroll
        for (int j = 0; j < 2; ++j) {
            int i = tid + j * 256;
            int r = i >> 2, c16 = i & 3;
            size_t goff = (size_t)(n0 + r) * 256 + kc * 32 + c16 * 8;
            uint32_t so = r * ROWB + c16 * 16;
            *(uint4*)(sBh + so) = *(const uint4*)(bth + goff);
            *(uint4*)(sBl + so) = *(const uint4*)(btl + goff);
        }
        __syncthreads();

        #pragma unroll
        for (int pass = 0; pass < 3; ++pass) {
            uint32_t uA = (pass < 2) ? uAh : uAl;
            uint32_t uB = (pass == 1) ? uBl : uBh;
            #pragma unroll
            for (int kk = 0; kk < 2; ++kk) {
                uint32_t af[MF][4], bf[4][2];
                #pragma unroll
                for (int mf = 0; mf < MF; ++mf)
                    ldm_x4(af[mf], uA + (mwarp + mf * 16 + arow) * ROWB + kk * 32 + ao16);
                #pragma unroll
                for (int nf = 0; nf < 4; ++nf)
                    ldm_x2(bf[nf], uB + (nwarp + nf * 8 + brow) * ROWB + kk * 32 + bo16);
                #pragma unroll
                for (int mf = 0; mf < MF; ++mf)
                    #pragma unroll
                    for (int nf = 0; nf < 4; ++nf)
                        mma_bf16(acc[mf][nf], af[mf], bf[nf]);
            }
        }
    }

    // ---- epilogue ----
    int tq = lane >> 2, tr = (lane & 3) * 2;
    #pragma unroll
    for (int mf = 0; mf < MF; ++mf) {
        #pragma unroll
        for (int half = 0; half < 2; ++half) {
            int m = m0 + mwarp + mf * 16 + tq + half * 8;
            size_t obase = (size_t)m * 256;
            int q = m & (T - 1);
            int qh = q >> 8, qc = q & 255;
            #pragma unroll
            for (int nf = 0; nf < 4; ++nf) {
                int n = n0 + nwarp + nf * 8 + tr;
                float2 v;
                if (SCALE) {
                    float s0 = g_S[(((n + 0) << 3) + qh) * 256 + qc];
                    float s1 = g_S[(((n + 1) << 3) + qh) * 256 + qc];
                    v.x = acc[mf][nf][half * 2 + 0] * s0;
                    v.y = acc[mf][nf][half * 2 + 1] * s1;
                } else {
                    v.x = acc[mf][nf][half * 2 + 0];
                    v.y = acc[mf][nf][half * 2 + 1];
                }
                *(float2*)(C + obase + n) = v;
            }
        }
    }
}

// ======================= exact 3-phase scan ================================
__global__ void scanA_kernel() {
    int d = threadIdx.x, g = blockIdx.x;
    int t0 = g * LTILE;
    float s = 0.f;
    #pragma unroll
    for (int i = 0; i < LTILE; ++i) {
        int t = t0 + i;
        float cv = (t == 0) ? 0.f : g_c[t * D + d];
        s = 0.9f * s + cv;
        g_S[t * D + d] = s;
    }
    g_carry[g * D + d] = s;
}
__global__ void scanB_kernel() {
    int d = threadIdx.x;
    float carry = 0.f;
    #pragma unroll
    for (int g = 0; g < NTILE; ++g) {
        float tmp = g_carry[g * D + d];
        g_pref[g * D + d] = carry;
        carry = G16 * carry + tmp;
    }
}
__global__ void scanC_kernel() {
    int d = threadIdx.x, g = blockIdx.x;
    int t0 = g * LTILE;
    if (g > 0) {
        float pref = g_pref[g * D + d];
        float p = 0.9f;
        #pragma unroll
        for (int i = 0; i < LTILE; ++i) {
            g_S[(t0 + i) * D + d] += p * pref;
            p *= 0.9f;
        }
    } else {
        g_S[d] = g_S[D + d];    // S[0] = r[1]
    }
}

// ======================= launch ============================================
extern "C" void kernel_launch(void* const* d_in, const int* in_sizes, int n_in,
                              void* d_out, int out_size) {
    const float* x  = (const float*)d_in[0];
    const float* Wq = (const float*)d_in[1];
    const float* Wk = (const float*)d_in[2];
    const float* Wv = (const float*)d_in[3];
    float* out = (float*)d_out;

    float* y_p; cudaGetSymbolAddress((void**)&y_p, g_y);
    float* c_p; cudaGetSymbolAddress((void**)&c_p, g_c);
    __nv_bfloat16* bqh_p; cudaGetSymbolAddress((void**)&bqh_p, g_bqh);
    __nv_bfloat16* bql_p; cudaGetSymbolAddress((void**)&bql_p, g_bql);
    __nv_bfloat16* bkh_p; cudaGetSymbolAddress((void**)&bkh_p, g_bkh);
    __nv_bfloat16* bkl_p; cudaGetSymbolAddress((void**)&bkl_p, g_bkl);

    prep_kernel<<<544, 256>>>(Wq, Wk, Wv);
    y_kernel<<<T, 256>>>(x);
    {
        dim3 grid(T / 32, 2);                 // c = y @ Wk   (128 CTAs)
        gemm_mma<1, false><<<grid, 256>>>(y_p, bkh_p, bkl_p, c_p);
    }
    scanA_kernel<<<NTILE, 256>>>();
    scanB_kernel<<<1, 256>>>();
    scanC_kernel<<<NTILE, 256>>>();
    {
        dim3 grid((Bsz * T) / 128, 2);        // out = scramble(S) * (x @ Wq)
        gemm_mma<4, true><<<grid, 256>>>(x, bqh_p, bql_p, out);
    }
}

// round 7
// speedup vs baseline: 1.2044x; 1.2044x over previous
#include <cuda_runtime.h>
#include <cuda_bf16.h>
#include <cstdint>

// ---------------------------------------------------------------------------
// RecurrentRetention: B=16, T=2048, D=256, gamma=0.9
//   vsum[b,t] = x[b,t,:].rowsum(Wv);  y[t,e] = sum_b vsum[b,t]*x[b,t,e]
//   c = y @ Wk;  r[t] = 0.9 r[t-1] + c[t] (exact 3-phase scan) -> S
//   out[b,q,p] = S[8p+(q>>8), q&255] * (x @ Wq)[b,q,p]
// Both GEMMs: warp mma.sync bf16 split (Ah*Bh + Ah*Bl + Al*Bh), ALL operands
// pre-split by producer kernels (split is register-side, nearly free there).
// ---------------------------------------------------------------------------

#define Bsz 16
#define T   2048
#define D   256
#define LTILE 8
#define NTILE (T / LTILE)             // 256
#define GL 0.43046721f                // 0.9^8

__device__ float g_wvsum[D];
__device__ float g_c[T * D];
__device__ float g_S[T * D];
__device__ float g_carry[NTILE * D];
__device__ float g_pref[NTILE * D];
__device__ __nv_bfloat16 g_xh[Bsz * T * D];
__device__ __nv_bfloat16 g_xl[Bsz * T * D];
__device__ __nv_bfloat16 g_yh[T * D];
__device__ __nv_bfloat16 g_yl[T * D];
__device__ __nv_bfloat16 g_bqh[D * D];  // Wq^T hi, [n][k]
__device__ __nv_bfloat16 g_bql[D * D];
__device__ __nv_bfloat16 g_bkh[D * D];  // Wk^T hi
__device__ __nv_bfloat16 g_bkl[D * D];

__device__ __forceinline__ uint32_t smem_u32(const void* p) {
    uint32_t a;
    asm("{ .reg .u64 t; cvta.to.shared.u64 t, %1; cvt.u32.u64 %0, t; }" : "=r"(a) : "l"(p));
    return a;
}
__device__ __forceinline__ void ldm_x4(uint32_t* r, uint32_t addr) {
    asm volatile("ldmatrix.sync.aligned.m8n8.x4.shared.b16 {%0,%1,%2,%3}, [%4];"
        : "=r"(r[0]), "=r"(r[1]), "=r"(r[2]), "=r"(r[3]) : "r"(addr));
}
__device__ __forceinline__ void ldm_x2(uint32_t* r, uint32_t addr) {
    asm volatile("ldmatrix.sync.aligned.m8n8.x2.shared.b16 {%0,%1}, [%2];"
        : "=r"(r[0]), "=r"(r[1]) : "r"(addr));
}
__device__ __forceinline__ void mma_bf16(float* c, const uint32_t* a, const uint32_t* b) {
    asm volatile(
        "mma.sync.aligned.m16n8k16.row.col.f32.bf16.bf16.f32 "
        "{%0,%1,%2,%3}, {%4,%5,%6,%7}, {%8,%9}, {%0,%1,%2,%3};"
        : "+f"(c[0]), "+f"(c[1]), "+f"(c[2]), "+f"(c[3])
        : "r"(a[0]), "r"(a[1]), "r"(a[2]), "r"(a[3]), "r"(b[0]), "r"(b[1]));
}

// ======================= prep: wvsum + Wq/Wk transpose-split ===============
__global__ void prep_kernel(const float* __restrict__ Wq, const float* __restrict__ Wk,
                            const float* __restrict__ Wv) {
    int bx = blockIdx.x, tid = threadIdx.x;
    if (bx < 256) {
        int k = bx, n = tid;
        float w = Wq[k * D + n];
        __nv_bfloat16 h = __float2bfloat16(w);
        g_bqh[n * D + k] = h;
        g_bql[n * D + k] = __float2bfloat16(w - __bfloat162float(h));
    } else if (bx < 512) {
        int k = bx - 256, n = tid;
        float w = Wk[k * D + n];
        __nv_bfloat16 h = __float2bfloat16(w);
        g_bkh[n * D + k] = h;
        g_bkl[n * D + k] = __float2bfloat16(w - __bfloat162float(h));
    } else {
        int row  = (bx - 512) * 8 + (tid >> 5);
        int lane = tid & 31;
        float p = 0.f;
        #pragma unroll
        for (int j = lane; j < D; j += 32) p += Wv[row * D + j];
        #pragma unroll
        for (int off = 16; off; off >>= 1) p += __shfl_xor_sync(0xffffffffu, p, off);
        if (lane == 0) g_wvsum[row] = p;
    }
}

// ======================= y kernel: y split + x split =======================
__global__ void y_kernel(const float* __restrict__ x) {
    __shared__ float xs[Bsz][D];
    __shared__ float vs[Bsz];
    __shared__ float wv[D];
    int t = blockIdx.x;
    int e = threadIdx.x;

    wv[e] = g_wvsum[e];
    #pragma unroll
    for (int b = 0; b < Bsz; ++b) {
        size_t idx = ((size_t)b * T + t) * D + e;
        float v = x[idx];
        xs[b][e] = v;
        __nv_bfloat16 h = __float2bfloat16(v);
        g_xh[idx] = h;
        g_xl[idx] = __float2bfloat16(v - __bfloat162float(h));
    }
    __syncthreads();

    int warp = e >> 5, lane = e & 31;
    #pragma unroll
    for (int rep = 0; rep < 2; ++rep) {
        int b = warp * 2 + rep;
        float p = 0.f;
        #pragma unroll
        for (int k = lane; k < D; k += 32) p += xs[b][k] * wv[k];
        #pragma unroll
        for (int off = 16; off; off >>= 1) p += __shfl_xor_sync(0xffffffffu, p, off);
        if (lane == 0) vs[b] = p;
    }
    __syncthreads();

    float acc = 0.f;
    #pragma unroll
    for (int b = 0; b < Bsz; ++b) acc += vs[b] * xs[b][e];
    __nv_bfloat16 h = __float2bfloat16(acc);
    g_yh[t * D + e] = h;
    g_yl[t * D + e] = __float2bfloat16(acc - __bfloat162float(h));
}

// ======================= unified mma GEMM (pre-split operands) =============
// C[m,n] = sum_k A[m,k]*Bt[n,k]; A, Bt pre-split bf16 hi/lo.
// CTA tile (MF*32) x 128, 8 warps = 2(m) x 4(n), warp tile (MF*16) x 32.
#define ROWB 80
template<int MF, bool SCALE>
__global__ void __launch_bounds__(256, 2)
gemm_mma(const __nv_bfloat16* __restrict__ ah, const __nv_bfloat16* __restrict__ al,
         const __nv_bfloat16* __restrict__ bth, const __nv_bfloat16* __restrict__ btl,
         float* __restrict__ C) {
    __shared__ char sAh[MF * 32 * ROWB], sAl[MF * 32 * ROWB];
    __shared__ char sBh[128 * ROWB],     sBl[128 * ROWB];

    int tid = threadIdx.x, wid = tid >> 5, lane = tid & 31;
    int m0 = blockIdx.x * (MF * 32), n0 = blockIdx.y * 128;
    int mwarp = (wid & 1) * (MF * 16), nwarp = (wid >> 1) * 32;

    uint32_t uAh = smem_u32(sAh), uAl = smem_u32(sAl);
    uint32_t uBh = smem_u32(sBh), uBl = smem_u32(sBl);

    float acc[MF][4][4] = {};

    int arow = lane & 15, ao16 = (lane >> 4) * 16;
    int brow = lane & 7,  bo16 = ((lane >> 3) & 1) * 16;

    for (int kc = 0; kc < 8; ++kc) {
        __syncthreads();
        // A chunk [MF*32 x 32] bf16 hi/lo (rows m0+r)
        #pragma unroll
        for (int i = tid; i < MF * 128; i += 256) {
            int r = i >> 2, c16 = i & 3;
            size_t goff = (size_t)(m0 + r) * 256 + kc * 32 + c16 * 8;
            uint32_t so = r * ROWB + c16 * 16;
            *(uint4*)(sAh + so) = *(const uint4*)(ah + goff);
            *(uint4*)(sAl + so) = *(const uint4*)(al + goff);
        }
        // B chunk [128 x 32] bf16 hi/lo (rows n0+r in [n][k] layout)
        #pragma unroll
        for (int j = 0; j < 2; ++j) {
            int i = tid + j * 256;
            int r = i >> 2, c16 = i & 3;
            size_t goff = (size_t)(n0 + r) * 256 + kc * 32 + c16 * 8;
            uint32_t so = r * ROWB + c16 * 16;
            *(uint4*)(sBh + so) = *(const uint4*)(bth + goff);
            *(uint4*)(sBl + so) = *(const uint4*)(btl + goff);
        }
        __syncthreads();

        #pragma unroll
        for (int pass = 0; pass < 3; ++pass) {
            uint32_t uA = (pass < 2) ? uAh : uAl;
            uint32_t uB = (pass == 1) ? uBl : uBh;
            #pragma unroll
            for (int kk = 0; kk < 2; ++kk) {
                uint32_t af[MF][4], bf[4][2];
                #pragma unroll
                for (int mf = 0; mf < MF; ++mf)
                    ldm_x4(af[mf], uA + (mwarp + mf * 16 + arow) * ROWB + kk * 32 + ao16);
                #pragma unroll
                for (int nf = 0; nf < 4; ++nf)
                    ldm_x2(bf[nf], uB + (nwarp + nf * 8 + brow) * ROWB + kk * 32 + bo16);
                #pragma unroll
                for (int mf = 0; mf < MF; ++mf)
                    #pragma unroll
                    for (int nf = 0; nf < 4; ++nf)
                        mma_bf16(acc[mf][nf], af[mf], bf[nf]);
            }
        }
    }

    // ---- epilogue ----
    int tq = lane >> 2, tr = (lane & 3) * 2;
    #pragma unroll
    for (int mf = 0; mf < MF; ++mf) {
        #pragma unroll
        for (int half = 0; half < 2; ++half) {
            int m = m0 + mwarp + mf * 16 + tq + half * 8;
            size_t obase = (size_t)m * 256;
            int q = m & (T - 1);
            int qh = q >> 8, qc = q & 255;
            #pragma unroll
            for (int nf = 0; nf < 4; ++nf) {
                int n = n0 + nwarp + nf * 8 + tr;
                float2 v;
                if (SCALE) {
                    float s0 = g_S[(((n + 0) << 3) + qh) * 256 + qc];
                    float s1 = g_S[(((n + 1) << 3) + qh) * 256 + qc];
                    v.x = acc[mf][nf][half * 2 + 0] * s0;
                    v.y = acc[mf][nf][half * 2 + 1] * s1;
                } else {
                    v.x = acc[mf][nf][half * 2 + 0];
                    v.y = acc[mf][nf][half * 2 + 1];
                }
                *(float2*)(C + obase + n) = v;
            }
        }
    }
}

// ======================= exact 3-phase scan ================================
__global__ void scanA_kernel() {
    int d = threadIdx.x, g = blockIdx.x;
    int t0 = g * LTILE;
    float s = 0.f;
    #pragma unroll
    for (int i = 0; i < LTILE; ++i) {
        int t = t0 + i;
        float cv = (t == 0) ? 0.f : g_c[t * D + d];
        s = 0.9f * s + cv;
        g_S[t * D + d] = s;
    }
    g_carry[g * D + d] = s;
}
__global__ void scanB_kernel() {
    int d = threadIdx.x;
    float carry = 0.f;
    #pragma unroll 8
    for (int g = 0; g < NTILE; ++g) {
        float tmp = g_carry[g * D + d];
        g_pref[g * D + d] = carry;
        carry = GL * carry + tmp;
    }
}
__global__ void scanC_kernel() {
    int d = threadIdx.x, g = blockIdx.x;
    int t0 = g * LTILE;
    if (g > 0) {
        float pref = g_pref[g * D + d];
        float p = 0.9f;
        #pragma unroll
        for (int i = 0; i < LTILE; ++i) {
            g_S[(t0 + i) * D + d] += p * pref;
            p *= 0.9f;
        }
    } else {
        g_S[d] = g_S[D + d];    // S[0] = r[1]
    }
}

// ======================= launch ============================================
extern "C" void kernel_launch(void* const* d_in, const int* in_sizes, int n_in,
                              void* d_out, int out_size) {
    const float* x  = (const float*)d_in[0];
    const float* Wq = (const float*)d_in[1];
    const float* Wk = (const float*)d_in[2];
    const float* Wv = (const float*)d_in[3];
    float* out = (float*)d_out;

    float* c_p; cudaGetSymbolAddress((void**)&c_p, g_c);
    __nv_bfloat16* xh_p; cudaGetSymbolAddress((void**)&xh_p, g_xh);
    __nv_bfloat16* xl_p; cudaGetSymbolAddress((void**)&xl_p, g_xl);
    __nv_bfloat16* yh_p; cudaGetSymbolAddress((void**)&yh_p, g_yh);
    __nv_bfloat16* yl_p; cudaGetSymbolAddress((void**)&yl_p, g_yl);
    __nv_bfloat16* bqh_p; cudaGetSymbolAddress((void**)&bqh_p, g_bqh);
    __nv_bfloat16* bql_p; cudaGetSymbolAddress((void**)&bql_p, g_bql);
    __nv_bfloat16* bkh_p; cudaGetSymbolAddress((void**)&bkh_p, g_bkh);
    __nv_bfloat16* bkl_p; cudaGetSymbolAddress((void**)&bkl_p, g_bkl);

    prep_kernel<<<544, 256>>>(Wq, Wk, Wv);
    y_kernel<<<T, 256>>>(x);
    {
        dim3 grid(T / 32, 2);                 // c = y @ Wk  (128 CTAs)
        gemm_mma<1, false><<<grid, 256>>>(yh_p, yl_p, bkh_p, bkl_p, c_p);
    }
    scanA_kernel<<<NTILE, 256>>>();
    scanB_kernel<<<1, 256>>>();
    scanC_kernel<<<NTILE, 256>>>();
    {
        dim3 grid((Bsz * T) / 128, 2);        // out = scramble(S) * (x @ Wq)
        gemm_mma<4, true><<<grid, 256>>>(xh_p, xl_p, bqh_p, bql_p, out);
    }
}